// round 14
// baseline (speedup 1.0000x reference)
#include <cuda_runtime.h>
#include <cuda_bf16.h>

// Fused shifted-window attention (Swin), round 14.
// = round 12 EXACT (475.2us proven base: R4 GEMM structure, rpbt smem bias,
// no-max softmax, ex2-folded scale, deferred normalization) with the QKV
// 9-pass loop and proj 3-pass loop fully unrolled so epilogue indexing
// (oc branches, /24 divisions, table bases) constant-folds away.

constexpr int TPB = 256;

// fragment-ordered weights: [pass(12)][ng(4)][kt(12)][lane(32)] x uint4
// pass 0..8 = qkv (9*64 out rows), pass 9..11 = proj.
__device__ uint4 g_wfrag[12 * 4 * 12 * 32];

// smem offsets (bytes)
constexpr int XBF_B = 0;       // [64][200] bf16 : gathered x, later attn-out
constexpr int QSH_B = 25600;   // [8][64][24] bf16, 48B rows
constexpr int KSH_B = 50176;   // same
constexpr int VSH_B = 74752;   // [8][24][72] bf16, 144B rows
constexpr int RPB_B = 102400;  // [8][228] f32 (pre-scaled by log2e)
constexpr int SMEM_BYTES = 109696;

__device__ __forceinline__ unsigned sptr(const void* p) {
    return (unsigned)__cvta_generic_to_shared(p);
}
__device__ __forceinline__ void ldmx4(unsigned a, unsigned* r) {
    asm volatile("ldmatrix.sync.aligned.m8n8.x4.shared.b16 {%0,%1,%2,%3}, [%4];"
        : "=r"(r[0]), "=r"(r[1]), "=r"(r[2]), "=r"(r[3]) : "r"(a));
}
__device__ __forceinline__ void ldmx2(unsigned a, unsigned* r) {
    asm volatile("ldmatrix.sync.aligned.m8n8.x2.shared.b16 {%0,%1}, [%2];"
        : "=r"(r[0]), "=r"(r[1]) : "r"(a));
}
__device__ __forceinline__ unsigned ldmx1(unsigned a) {
    unsigned r;
    asm volatile("ldmatrix.sync.aligned.m8n8.x1.shared.b16 {%0}, [%1];"
        : "=r"(r) : "r"(a));
    return r;
}
__device__ __forceinline__ void mma16(float* c, const unsigned* a, const unsigned* b) {
    asm volatile("mma.sync.aligned.m16n8k16.row.col.f32.bf16.bf16.f32 "
        "{%0,%1,%2,%3}, {%4,%5,%6,%7}, {%8,%9}, {%0,%1,%2,%3};"
        : "+f"(c[0]), "+f"(c[1]), "+f"(c[2]), "+f"(c[3])
        : "r"(a[0]), "r"(a[1]), "r"(a[2]), "r"(a[3]), "r"(b[0]), "r"(b[1]));
}
__device__ __forceinline__ void mma8(float* c, const unsigned* a, unsigned b) {
    asm volatile("mma.sync.aligned.m16n8k8.row.col.f32.bf16.bf16.f32 "
        "{%0,%1,%2,%3}, {%4,%5}, {%6}, {%0,%1,%2,%3};"
        : "+f"(c[0]), "+f"(c[1]), "+f"(c[2]), "+f"(c[3])
        : "r"(a[0]), "r"(a[1]), "r"(b));
}
__device__ __forceinline__ unsigned packbf(float a, float b) {
    __nv_bfloat162 t = __floats2bfloat162_rn(a, b);
    return *(unsigned*)&t;
}
__device__ __forceinline__ float ex2f(float x) {
    float r;
    asm("ex2.approx.f32 %0, %1;" : "=f"(r) : "f"(x));
    return r;
}

// one thread per output u32 (73728 total)
__global__ void convert_weights(const float* __restrict__ qkv_w,
                                const float* __restrict__ proj_w)
{
    int idx = blockIdx.x * TPB + threadIdx.x;
    if (idx >= 12*4*12*32*4) return;
    int q    = idx & 3;
    int tmp  = idx >> 2;          // uint4 index
    int lane = tmp & 31;
    int tmp2 = tmp >> 5;
    int kt   = tmp2 % 12;
    int tmp3 = tmp2 / 12;
    int ng   = tmp3 & 3;
    int p    = tmp3 >> 2;
    int g    = lane >> 2;
    int tig  = lane & 3;
    int j    = q >> 1;
    int half = q & 1;
    int row  = p*64 + ng*16 + j*8 + g;            // 0..767
    int col2 = kt*8 + tig + half*4;               // u32 column
    const float* src = (row < 576) ? (qkv_w + row*192)
                                   : (proj_w + (row - 576)*192);
    ((unsigned*)g_wfrag)[idx] = packbf(src[2*col2], src[2*col2 + 1]);
}

__global__ void __launch_bounds__(TPB, 2)
swin14(const float* __restrict__ x,
       const float* __restrict__ qkv_b,
       const float* __restrict__ proj_b,
       const float* __restrict__ rpb,
       float* __restrict__ out)
{
    extern __shared__ char smem[];
    __nv_bfloat16* xbf = (__nv_bfloat16*)(smem + XBF_B);
    float* rpbt = (float*)(smem + RPB_B);

    const int tid  = threadIdx.x;
    const int lane = tid & 31;
    const int wid  = tid >> 5;
    const int g    = lane >> 2;
    const int tig  = lane & 3;

    const int win = blockIdx.x;
    const int b   = win >> 10;
    const int wr  = (win >> 5) & 31;
    const int wc  = win & 31;
    const int hbase = wr*8 + 4;
    const int wbase = wc*8 + 4;
    const bool er = (wr == 31), ec = (wc == 31);
    const float LOG2E = 1.4426950408889634f;
    const float SCALE = 0.2041241452319315f * LOG2E;   // 24^-0.5 * log2(e)
    const float MASKC = 100.0f * LOG2E;

    const float* xb   = x   + ((b*192) << 16);
    float*       outb = out + ((b*192) << 16);

    // ---------------- prologue ----------------
    for (int i = tid; i < 1800; i += TPB)
        rpbt[(i & 7)*228 + (i >> 3)] = rpb[i] * LOG2E;
    for (int idx = tid; idx < 192*64; idx += TPB) {
        int c = idx >> 6, t = idx & 63;
        int hh = (hbase + (t >> 3)) & 255;
        int ww = (wbase + (t & 7)) & 255;
        xbf[t*200 + c] = __float2bfloat16(xb[(c << 16) + (hh << 8) + ww]);
    }
    __syncthreads();   // (1)

    const int mg = wid >> 2;   // 0..1 : rows mg*32
    const int ng = wid & 3;    // 0..3 : cols ng*16

    const unsigned aA0 = sptr(smem + XBF_B) + ((mg*32 + (lane & 15))*200 + (lane >> 4)*8)*2;
    const unsigned aA1 = aA0 + 16*400;

    // ================= QKV GEMM: 9 passes x 64 out-chans, fully unrolled =================
    #pragma unroll
    for (int p = 0; p < 9; ++p) {
        const int oc = p / 3;
        const int cbase = (p - oc*3)*64;
        const uint4* bp = g_wfrag + ((p*4 + ng)*12)*32 + lane;

        float acc[2][2][4];
        #pragma unroll
        for (int i = 0; i < 2; ++i)
            #pragma unroll
            for (int j = 0; j < 2; ++j)
                acc[i][j][0]=acc[i][j][1]=acc[i][j][2]=acc[i][j][3]=0.f;

        #pragma unroll
        for (int kt = 0; kt < 12; ++kt) {
            uint4 w = bp[kt*32];
            unsigned bf0[2] = {w.x, w.y};
            unsigned bf1[2] = {w.z, w.w};
            unsigned af[2][4];
            ldmx4(aA0 + kt*32, af[0]);
            ldmx4(aA1 + kt*32, af[1]);
            mma16(acc[0][0], af[0], bf0);
            mma16(acc[0][1], af[0], bf1);
            mma16(acc[1][0], af[1], bf0);
            mma16(acc[1][1], af[1], bf1);
        }
        // epilogue -> q/k/v smem (+bias; q pre-scaled by 24^-0.5*log2e)
        #pragma unroll
        for (int mt = 0; mt < 2; ++mt) {
            #pragma unroll
            for (int j = 0; j < 2; ++j) {
                int cg = cbase + ng*16 + j*8 + 2*tig;
                int h2 = cg / 24;
                int d  = cg - h2*24;
                float2 bb = *(const float2*)(qkv_b + oc*192 + cg);
                int r0 = mg*32 + mt*16 + g;
                float c0 = acc[mt][j][0] + bb.x, c1 = acc[mt][j][1] + bb.y;
                float c2 = acc[mt][j][2] + bb.x, c3 = acc[mt][j][3] + bb.y;
                if (oc == 0) {
                    c0 *= SCALE; c1 *= SCALE; c2 *= SCALE; c3 *= SCALE;
                    *(__nv_bfloat162*)(smem + QSH_B + (h2*64 + r0    )*48 + d*2) = __floats2bfloat162_rn(c0, c1);
                    *(__nv_bfloat162*)(smem + QSH_B + (h2*64 + r0 + 8)*48 + d*2) = __floats2bfloat162_rn(c2, c3);
                } else if (oc == 1) {
                    *(__nv_bfloat162*)(smem + KSH_B + (h2*64 + r0    )*48 + d*2) = __floats2bfloat162_rn(c0, c1);
                    *(__nv_bfloat162*)(smem + KSH_B + (h2*64 + r0 + 8)*48 + d*2) = __floats2bfloat162_rn(c2, c3);
                } else {
                    __nv_bfloat16* vv = (__nv_bfloat16*)(smem + VSH_B) + (h2*24 + d)*72;
                    vv[r0]          = __float2bfloat16(c0);
                    vv[72 + r0]     = __float2bfloat16(c1);
                    vv[r0 + 8]      = __float2bfloat16(c2);
                    vv[72 + r0 + 8] = __float2bfloat16(c3);
                }
            }
        }
    }
    __syncthreads();   // (2) q/k/v visible; xbf reads done

    // ================= attention: warp h = head h, register-resident =================
    {
        const int h = wid;
        const float* rp = rpbt + h*228;
        const unsigned qb16 = sptr(smem + QSH_B) + (h*64 + (lane & 15))*48 + (lane >> 4)*16;
        const unsigned qb8  = sptr(smem + QSH_B) + (h*64 + (lane & 15))*48 + 32;
        const unsigned kb16 = sptr(smem + KSH_B) + (h*64 + (lane & 7))*48 + ((lane >> 3) & 1)*16;
        const unsigned kb8  = sptr(smem + KSH_B) + (h*64 + (lane & 7))*48 + 32;
        const unsigned vb   = sptr(smem + VSH_B) + (h*24 + (lane & 7))*144 + ((lane >> 3) & 1)*16;

        int regjE[2];
        #pragma unroll
        for (int e = 0; e < 2; ++e)
            regjE[e] = ec ? (((2*tig + e) < 4) ? 1 : 2) : 0;
        const int regiX = ec ? ((g < 4) ? 1 : 2) : 0;

        #pragma unroll
        for (int mp = 0; mp < 2; ++mp) {
            unsigned qf[2][4], qf8v[2][2];
            #pragma unroll
            for (int mt = 0; mt < 2; ++mt) {
                ldmx4(qb16 + (mp*32 + mt*16)*48, qf[mt]);
                ldmx2(qb8  + (mp*32 + mt*16)*48, qf8v[mt]);
            }
            float s[2][8][4];
            #pragma unroll
            for (int jj = 0; jj < 8; ++jj) {
                unsigned kf[2];
                ldmx2(kb16 + jj*384, kf);
                unsigned k8 = ldmx1(kb8 + jj*384);
                #pragma unroll
                for (int mt = 0; mt < 2; ++mt) {
                    s[mt][jj][0]=s[mt][jj][1]=s[mt][jj][2]=s[mt][jj][3]=0.f;
                    mma16(s[mt][jj], qf[mt], kf);
                    mma8 (s[mt][jj], qf8v[mt], k8);
                }
            }
            // bias + mask + exp2 (no max-sub); normalization deferred
            float inv[2][2];
            #pragma unroll
            for (int mt = 0; mt < 2; ++mt) {
                #pragma unroll
                for (int half = 0; half < 2; ++half) {
                    int yi = mp*4 + mt*2 + half;
                    int regi = (er ? ((yi < 4) ? 3 : 6) : 0) + regiX;
                    float sum = 0.f;
                    #pragma unroll
                    for (int jj = 0; jj < 8; ++jj) {
                        int rjY = er ? ((jj < 4) ? 3 : 6) : 0;
                        #pragma unroll
                        for (int e = 0; e < 2; ++e) {
                            float val = s[mt][jj][half*2 + e];
                            int idx = (yi - jj + 7)*15 + (g - (2*tig + e) + 7);
                            val += rp[idx];
                            if (regi != (rjY + regjE[e])) val -= MASKC;
                            float ev = ex2f(val);
                            s[mt][jj][half*2 + e] = ev;
                            sum += ev;
                        }
                    }
                    sum += __shfl_xor_sync(0xffffffffu, sum, 1);
                    sum += __shfl_xor_sync(0xffffffffu, sum, 2);
                    inv[mt][half] = 1.f / sum;
                }
            }
            // repack unnormalized P -> a-frags; O = P @ V
            unsigned pf[2][4][4];
            #pragma unroll
            for (int mt = 0; mt < 2; ++mt)
                #pragma unroll
                for (int kt = 0; kt < 4; ++kt) {
                    pf[mt][kt][0] = packbf(s[mt][2*kt][0],     s[mt][2*kt][1]);
                    pf[mt][kt][1] = packbf(s[mt][2*kt][2],     s[mt][2*kt][3]);
                    pf[mt][kt][2] = packbf(s[mt][2*kt + 1][0], s[mt][2*kt + 1][1]);
                    pf[mt][kt][3] = packbf(s[mt][2*kt + 1][2], s[mt][2*kt + 1][3]);
                }
            float o[2][3][4];
            #pragma unroll
            for (int mt = 0; mt < 2; ++mt)
                #pragma unroll
                for (int vn = 0; vn < 3; ++vn)
                    o[mt][vn][0]=o[mt][vn][1]=o[mt][vn][2]=o[mt][vn][3]=0.f;
            #pragma unroll
            for (int kt = 0; kt < 4; ++kt)
                #pragma unroll
                for (int vn = 0; vn < 3; ++vn) {
                    unsigned vf[2];
                    ldmx2(vb + vn*1152 + kt*32, vf);
                    mma16(o[0][vn], pf[0][kt], vf);
                    mma16(o[1][vn], pf[1][kt], vf);
                }
            // write O (scaled by deferred 1/sum) -> attn-out, [token][h*24+d]
            #pragma unroll
            for (int mt = 0; mt < 2; ++mt) {
                int r0 = mp*32 + mt*16 + g;
                float iv0 = inv[mt][0], iv1 = inv[mt][1];
                #pragma unroll
                for (int vn = 0; vn < 3; ++vn) {
                    int col = h*24 + vn*8 + 2*tig;
                    *(__nv_bfloat162*)(smem + XBF_B + r0*400 + col*2)
                        = __floats2bfloat162_rn(o[mt][vn][0]*iv0, o[mt][vn][1]*iv0);
                    *(__nv_bfloat162*)(smem + XBF_B + (r0 + 8)*400 + col*2)
                        = __floats2bfloat162_rn(o[mt][vn][2]*iv1, o[mt][vn][3]*iv1);
                }
            }
        }
    }
    __syncthreads();   // (3) attn-out visible

    // ================= proj GEMM + bias + residual + scatter, unrolled =================
    #pragma unroll
    for (int p = 0; p < 3; ++p) {
        const uint4* bp = g_wfrag + (((9 + p)*4 + ng)*12)*32 + lane;

        float acc[2][2][4];
        #pragma unroll
        for (int i = 0; i < 2; ++i)
            #pragma unroll
            for (int j = 0; j < 2; ++j)
                acc[i][j][0]=acc[i][j][1]=acc[i][j][2]=acc[i][j][3]=0.f;

        #pragma unroll
        for (int kt = 0; kt < 12; ++kt) {
            uint4 w = bp[kt*32];
            unsigned bf0[2] = {w.x, w.y};
            unsigned bf1[2] = {w.z, w.w};
            unsigned af[2][4];
            ldmx4(aA0 + kt*32, af[0]);
            ldmx4(aA1 + kt*32, af[1]);
            mma16(acc[0][0], af[0], bf0);
            mma16(acc[0][1], af[0], bf1);
            mma16(acc[1][0], af[1], bf0);
            mma16(acc[1][1], af[1], bf1);
        }
        #pragma unroll
        for (int mt = 0; mt < 2; ++mt) {
            #pragma unroll
            for (int j = 0; j < 2; ++j) {
                int ch = p*64 + ng*16 + j*8 + 2*tig;
                float2 bb = *(const float2*)(proj_b + ch);
                int r0 = mg*32 + mt*16 + g, r1 = r0 + 8;
                int a0 = (((hbase + (r0 >> 3)) & 255) << 8) | ((wbase + (r0 & 7)) & 255);
                int a1 = (((hbase + (r1 >> 3)) & 255) << 8) | ((wbase + (r1 & 7)) & 255);
                const float* xc0 = xb + (ch << 16);
                const float* xc1 = xc0 + 65536;
                float* oc0 = outb + (ch << 16);
                float* oc1 = oc0 + 65536;
                oc0[a0] = acc[mt][j][0] + bb.x + xc0[a0];
                oc1[a0] = acc[mt][j][1] + bb.y + xc1[a0];
                oc0[a1] = acc[mt][j][2] + bb.x + xc0[a1];
                oc1[a1] = acc[mt][j][3] + bb.y + xc1[a1];
            }
        }
    }
}

extern "C" void kernel_launch(void* const* d_in, const int* in_sizes, int n_in,
                              void* d_out, int out_size)
{
    const float* x      = (const float*)d_in[0];
    const float* qkv_w  = (const float*)d_in[1];
    const float* qkv_b  = (const float*)d_in[2];
    const float* proj_w = (const float*)d_in[3];
    const float* proj_b = (const float*)d_in[4];
    const float* rpb    = (const float*)d_in[5];
    float* out = (float*)d_out;

    convert_weights<<<(12*4*12*32*4 + TPB - 1)/TPB, TPB>>>(qkv_w, proj_w);

    cudaFuncSetAttribute(swin14,
                         cudaFuncAttributeMaxDynamicSharedMemorySize, SMEM_BYTES);
    swin14<<<4096, TPB, SMEM_BYTES>>>(x, qkv_b, proj_b, rpb, out);
}

// round 15
// speedup vs baseline: 1.0709x; 1.0709x over previous
#include <cuda_runtime.h>
#include <cuda_bf16.h>

// Fused shifted-window attention (Swin), round 15.
// = round 12 EXACT (475.2us proven) with ONE change: the QKV 9-pass loop is
// restructured as oc(3, unrolled) x pp(3, dynamic). oc becomes compile-time,
// deleting the q/k/v branch tree from every epilogue, at only ~3x GEMM body
// code size (R14 showed 9x blew the I-cache; 3x should not).

constexpr int TPB = 256;

// fragment-ordered weights: [pass(12)][ng(4)][kt(12)][lane(32)] x uint4
// pass 0..8 = qkv (9*64 out rows), pass 9..11 = proj.
__device__ uint4 g_wfrag[12 * 4 * 12 * 32];

// smem offsets (bytes)
constexpr int XBF_B = 0;       // [64][200] bf16 : gathered x, later attn-out
constexpr int QSH_B = 25600;   // [8][64][24] bf16, 48B rows
constexpr int KSH_B = 50176;   // same
constexpr int VSH_B = 74752;   // [8][24][72] bf16, 144B rows
constexpr int RPB_B = 102400;  // [8][228] f32 (pre-scaled by log2e)
constexpr int SMEM_BYTES = 109696;

__device__ __forceinline__ unsigned sptr(const void* p) {
    return (unsigned)__cvta_generic_to_shared(p);
}
__device__ __forceinline__ void ldmx4(unsigned a, unsigned* r) {
    asm volatile("ldmatrix.sync.aligned.m8n8.x4.shared.b16 {%0,%1,%2,%3}, [%4];"
        : "=r"(r[0]), "=r"(r[1]), "=r"(r[2]), "=r"(r[3]) : "r"(a));
}
__device__ __forceinline__ void ldmx2(unsigned a, unsigned* r) {
    asm volatile("ldmatrix.sync.aligned.m8n8.x2.shared.b16 {%0,%1}, [%2];"
        : "=r"(r[0]), "=r"(r[1]) : "r"(a));
}
__device__ __forceinline__ unsigned ldmx1(unsigned a) {
    unsigned r;
    asm volatile("ldmatrix.sync.aligned.m8n8.x1.shared.b16 {%0}, [%1];"
        : "=r"(r) : "r"(a));
    return r;
}
__device__ __forceinline__ void mma16(float* c, const unsigned* a, const unsigned* b) {
    asm volatile("mma.sync.aligned.m16n8k16.row.col.f32.bf16.bf16.f32 "
        "{%0,%1,%2,%3}, {%4,%5,%6,%7}, {%8,%9}, {%0,%1,%2,%3};"
        : "+f"(c[0]), "+f"(c[1]), "+f"(c[2]), "+f"(c[3])
        : "r"(a[0]), "r"(a[1]), "r"(a[2]), "r"(a[3]), "r"(b[0]), "r"(b[1]));
}
__device__ __forceinline__ void mma8(float* c, const unsigned* a, unsigned b) {
    asm volatile("mma.sync.aligned.m16n8k8.row.col.f32.bf16.bf16.f32 "
        "{%0,%1,%2,%3}, {%4,%5}, {%6}, {%0,%1,%2,%3};"
        : "+f"(c[0]), "+f"(c[1]), "+f"(c[2]), "+f"(c[3])
        : "r"(a[0]), "r"(a[1]), "r"(b));
}
__device__ __forceinline__ unsigned packbf(float a, float b) {
    __nv_bfloat162 t = __floats2bfloat162_rn(a, b);
    return *(unsigned*)&t;
}
__device__ __forceinline__ float ex2f(float x) {
    float r;
    asm("ex2.approx.f32 %0, %1;" : "=f"(r) : "f"(x));
    return r;
}

// one thread per output u32 (73728 total)
__global__ void convert_weights(const float* __restrict__ qkv_w,
                                const float* __restrict__ proj_w)
{
    int idx = blockIdx.x * TPB + threadIdx.x;
    if (idx >= 12*4*12*32*4) return;
    int q    = idx & 3;
    int tmp  = idx >> 2;          // uint4 index
    int lane = tmp & 31;
    int tmp2 = tmp >> 5;
    int kt   = tmp2 % 12;
    int tmp3 = tmp2 / 12;
    int ng   = tmp3 & 3;
    int p    = tmp3 >> 2;
    int g    = lane >> 2;
    int tig  = lane & 3;
    int j    = q >> 1;
    int half = q & 1;
    int row  = p*64 + ng*16 + j*8 + g;            // 0..767
    int col2 = kt*8 + tig + half*4;               // u32 column
    const float* src = (row < 576) ? (qkv_w + row*192)
                                   : (proj_w + (row - 576)*192);
    ((unsigned*)g_wfrag)[idx] = packbf(src[2*col2], src[2*col2 + 1]);
}

__global__ void __launch_bounds__(TPB, 2)
swin15(const float* __restrict__ x,
       const float* __restrict__ qkv_b,
       const float* __restrict__ proj_b,
       const float* __restrict__ rpb,
       float* __restrict__ out)
{
    extern __shared__ char smem[];
    __nv_bfloat16* xbf = (__nv_bfloat16*)(smem + XBF_B);
    float* rpbt = (float*)(smem + RPB_B);

    const int tid  = threadIdx.x;
    const int lane = tid & 31;
    const int wid  = tid >> 5;
    const int g    = lane >> 2;
    const int tig  = lane & 3;

    const int win = blockIdx.x;
    const int b   = win >> 10;
    const int wr  = (win >> 5) & 31;
    const int wc  = win & 31;
    const int hbase = wr*8 + 4;
    const int wbase = wc*8 + 4;
    const bool er = (wr == 31), ec = (wc == 31);
    const float LOG2E = 1.4426950408889634f;
    const float SCALE = 0.2041241452319315f * LOG2E;   // 24^-0.5 * log2(e)
    const float MASKC = 100.0f * LOG2E;

    const float* xb   = x   + ((b*192) << 16);
    float*       outb = out + ((b*192) << 16);

    // ---------------- prologue ----------------
    for (int i = tid; i < 1800; i += TPB)
        rpbt[(i & 7)*228 + (i >> 3)] = rpb[i] * LOG2E;
    for (int idx = tid; idx < 192*64; idx += TPB) {
        int c = idx >> 6, t = idx & 63;
        int hh = (hbase + (t >> 3)) & 255;
        int ww = (wbase + (t & 7)) & 255;
        xbf[t*200 + c] = __float2bfloat16(xb[(c << 16) + (hh << 8) + ww]);
    }
    __syncthreads();   // (1)

    const int mg = wid >> 2;   // 0..1 : rows mg*32
    const int ng = wid & 3;    // 0..3 : cols ng*16

    const unsigned aA0 = sptr(smem + XBF_B) + ((mg*32 + (lane & 15))*200 + (lane >> 4)*8)*2;
    const unsigned aA1 = aA0 + 16*400;

    // ===== QKV GEMM: oc unrolled (compile-time q/k/v select), pp dynamic =====
    #pragma unroll
    for (int oc = 0; oc < 3; ++oc) {
        for (int pp = 0; pp < 3; ++pp) {
            const int cbase = pp*64;
            const uint4* bp = g_wfrag + (((oc*3 + pp)*4 + ng)*12)*32 + lane;

            float acc[2][2][4];
            #pragma unroll
            for (int i = 0; i < 2; ++i)
                #pragma unroll
                for (int j = 0; j < 2; ++j)
                    acc[i][j][0]=acc[i][j][1]=acc[i][j][2]=acc[i][j][3]=0.f;

            #pragma unroll
            for (int kt = 0; kt < 12; ++kt) {
                uint4 w = bp[kt*32];
                unsigned bf0[2] = {w.x, w.y};
                unsigned bf1[2] = {w.z, w.w};
                unsigned af[2][4];
                ldmx4(aA0 + kt*32, af[0]);
                ldmx4(aA1 + kt*32, af[1]);
                mma16(acc[0][0], af[0], bf0);
                mma16(acc[0][1], af[0], bf1);
                mma16(acc[1][0], af[1], bf0);
                mma16(acc[1][1], af[1], bf1);
            }
            // epilogue -> q/k/v smem (+bias; q pre-scaled); oc compile-time
            #pragma unroll
            for (int mt = 0; mt < 2; ++mt) {
                #pragma unroll
                for (int j = 0; j < 2; ++j) {
                    int cg = cbase + ng*16 + j*8 + 2*tig;
                    int h2 = cg / 24;
                    int d  = cg - h2*24;
                    float2 bb = *(const float2*)(qkv_b + oc*192 + cg);
                    int r0 = mg*32 + mt*16 + g;
                    float c0 = acc[mt][j][0] + bb.x, c1 = acc[mt][j][1] + bb.y;
                    float c2 = acc[mt][j][2] + bb.x, c3 = acc[mt][j][3] + bb.y;
                    if (oc == 0) {
                        c0 *= SCALE; c1 *= SCALE; c2 *= SCALE; c3 *= SCALE;
                        *(__nv_bfloat162*)(smem + QSH_B + (h2*64 + r0    )*48 + d*2) = __floats2bfloat162_rn(c0, c1);
                        *(__nv_bfloat162*)(smem + QSH_B + (h2*64 + r0 + 8)*48 + d*2) = __floats2bfloat162_rn(c2, c3);
                    } else if (oc == 1) {
                        *(__nv_bfloat162*)(smem + KSH_B + (h2*64 + r0    )*48 + d*2) = __floats2bfloat162_rn(c0, c1);
                        *(__nv_bfloat162*)(smem + KSH_B + (h2*64 + r0 + 8)*48 + d*2) = __floats2bfloat162_rn(c2, c3);
                    } else {
                        __nv_bfloat16* vv = (__nv_bfloat16*)(smem + VSH_B) + (h2*24 + d)*72;
                        vv[r0]          = __float2bfloat16(c0);
                        vv[72 + r0]     = __float2bfloat16(c1);
                        vv[r0 + 8]      = __float2bfloat16(c2);
                        vv[72 + r0 + 8] = __float2bfloat16(c3);
                    }
                }
            }
        }
    }
    __syncthreads();   // (2) q/k/v visible; xbf reads done

    // ================= attention: warp h = head h, register-resident =================
    {
        const int h = wid;
        const float* rp = rpbt + h*228;
        const unsigned qb16 = sptr(smem + QSH_B) + (h*64 + (lane & 15))*48 + (lane >> 4)*16;
        const unsigned qb8  = sptr(smem + QSH_B) + (h*64 + (lane & 15))*48 + 32;
        const unsigned kb16 = sptr(smem + KSH_B) + (h*64 + (lane & 7))*48 + ((lane >> 3) & 1)*16;
        const unsigned kb8  = sptr(smem + KSH_B) + (h*64 + (lane & 7))*48 + 32;
        const unsigned vb   = sptr(smem + VSH_B) + (h*24 + (lane & 7))*144 + ((lane >> 3) & 1)*16;

        int regjE[2];
        #pragma unroll
        for (int e = 0; e < 2; ++e)
            regjE[e] = ec ? (((2*tig + e) < 4) ? 1 : 2) : 0;
        const int regiX = ec ? ((g < 4) ? 1 : 2) : 0;

        #pragma unroll
        for (int mp = 0; mp < 2; ++mp) {
            unsigned qf[2][4], qf8v[2][2];
            #pragma unroll
            for (int mt = 0; mt < 2; ++mt) {
                ldmx4(qb16 + (mp*32 + mt*16)*48, qf[mt]);
                ldmx2(qb8  + (mp*32 + mt*16)*48, qf8v[mt]);
            }
            float s[2][8][4];
            #pragma unroll
            for (int jj = 0; jj < 8; ++jj) {
                unsigned kf[2];
                ldmx2(kb16 + jj*384, kf);
                unsigned k8 = ldmx1(kb8 + jj*384);
                #pragma unroll
                for (int mt = 0; mt < 2; ++mt) {
                    s[mt][jj][0]=s[mt][jj][1]=s[mt][jj][2]=s[mt][jj][3]=0.f;
                    mma16(s[mt][jj], qf[mt], kf);
                    mma8 (s[mt][jj], qf8v[mt], k8);
                }
            }
            // bias + mask + exp2 (no max-sub); normalization deferred
            float inv[2][2];
            #pragma unroll
            for (int mt = 0; mt < 2; ++mt) {
                #pragma unroll
                for (int half = 0; half < 2; ++half) {
                    int yi = mp*4 + mt*2 + half;
                    int regi = (er ? ((yi < 4) ? 3 : 6) : 0) + regiX;
                    float sum = 0.f;
                    #pragma unroll
                    for (int jj = 0; jj < 8; ++jj) {
                        int rjY = er ? ((jj < 4) ? 3 : 6) : 0;
                        #pragma unroll
                        for (int e = 0; e < 2; ++e) {
                            float val = s[mt][jj][half*2 + e];
                            int idx = (yi - jj + 7)*15 + (g - (2*tig + e) + 7);
                            val += rp[idx];
                            if (regi != (rjY + regjE[e])) val -= MASKC;
                            float ev = ex2f(val);
                            s[mt][jj][half*2 + e] = ev;
                            sum += ev;
                        }
                    }
                    sum += __shfl_xor_sync(0xffffffffu, sum, 1);
                    sum += __shfl_xor_sync(0xffffffffu, sum, 2);
                    inv[mt][half] = 1.f / sum;
                }
            }
            // repack unnormalized P -> a-frags; O = P @ V
            unsigned pf[2][4][4];
            #pragma unroll
            for (int mt = 0; mt < 2; ++mt)
                #pragma unroll
                for (int kt = 0; kt < 4; ++kt) {
                    pf[mt][kt][0] = packbf(s[mt][2*kt][0],     s[mt][2*kt][1]);
                    pf[mt][kt][1] = packbf(s[mt][2*kt][2],     s[mt][2*kt][3]);
                    pf[mt][kt][2] = packbf(s[mt][2*kt + 1][0], s[mt][2*kt + 1][1]);
                    pf[mt][kt][3] = packbf(s[mt][2*kt + 1][2], s[mt][2*kt + 1][3]);
                }
            float o[2][3][4];
            #pragma unroll
            for (int mt = 0; mt < 2; ++mt)
                #pragma unroll
                for (int vn = 0; vn < 3; ++vn)
                    o[mt][vn][0]=o[mt][vn][1]=o[mt][vn][2]=o[mt][vn][3]=0.f;
            #pragma unroll
            for (int kt = 0; kt < 4; ++kt)
                #pragma unroll
                for (int vn = 0; vn < 3; ++vn) {
                    unsigned vf[2];
                    ldmx2(vb + vn*1152 + kt*32, vf);
                    mma16(o[0][vn], pf[0][kt], vf);
                    mma16(o[1][vn], pf[1][kt], vf);
                }
            // write O (scaled by deferred 1/sum) -> attn-out, [token][h*24+d]
            #pragma unroll
            for (int mt = 0; mt < 2; ++mt) {
                int r0 = mp*32 + mt*16 + g;
                float iv0 = inv[mt][0], iv1 = inv[mt][1];
                #pragma unroll
                for (int vn = 0; vn < 3; ++vn) {
                    int col = h*24 + vn*8 + 2*tig;
                    *(__nv_bfloat162*)(smem + XBF_B + r0*400 + col*2)
                        = __floats2bfloat162_rn(o[mt][vn][0]*iv0, o[mt][vn][1]*iv0);
                    *(__nv_bfloat162*)(smem + XBF_B + (r0 + 8)*400 + col*2)
                        = __floats2bfloat162_rn(o[mt][vn][2]*iv1, o[mt][vn][3]*iv1);
                }
            }
        }
    }
    __syncthreads();   // (3) attn-out visible

    // ================= proj GEMM + bias + residual + scatter =================
    for (int p = 0; p < 3; ++p) {
        const uint4* bp = g_wfrag + (((9 + p)*4 + ng)*12)*32 + lane;

        float acc[2][2][4];
        #pragma unroll
        for (int i = 0; i < 2; ++i)
            #pragma unroll
            for (int j = 0; j < 2; ++j)
                acc[i][j][0]=acc[i][j][1]=acc[i][j][2]=acc[i][j][3]=0.f;

        #pragma unroll
        for (int kt = 0; kt < 12; ++kt) {
            uint4 w = bp[kt*32];
            unsigned bf0[2] = {w.x, w.y};
            unsigned bf1[2] = {w.z, w.w};
            unsigned af[2][4];
            ldmx4(aA0 + kt*32, af[0]);
            ldmx4(aA1 + kt*32, af[1]);
            mma16(acc[0][0], af[0], bf0);
            mma16(acc[0][1], af[0], bf1);
            mma16(acc[1][0], af[1], bf0);
            mma16(acc[1][1], af[1], bf1);
        }
        #pragma unroll
        for (int mt = 0; mt < 2; ++mt) {
            #pragma unroll
            for (int j = 0; j < 2; ++j) {
                int ch = p*64 + ng*16 + j*8 + 2*tig;
                float2 bb = *(const float2*)(proj_b + ch);
                int r0 = mg*32 + mt*16 + g, r1 = r0 + 8;
                int a0 = (((hbase + (r0 >> 3)) & 255) << 8) | ((wbase + (r0 & 7)) & 255);
                int a1 = (((hbase + (r1 >> 3)) & 255) << 8) | ((wbase + (r1 & 7)) & 255);
                const float* xc0 = xb + (ch << 16);
                const float* xc1 = xc0 + 65536;
                float* oc0 = outb + (ch << 16);
                float* oc1 = oc0 + 65536;
                oc0[a0] = acc[mt][j][0] + bb.x + xc0[a0];
                oc1[a0] = acc[mt][j][1] + bb.y + xc1[a0];
                oc0[a1] = acc[mt][j][2] + bb.x + xc0[a1];
                oc1[a1] = acc[mt][j][3] + bb.y + xc1[a1];
            }
        }
    }
}

extern "C" void kernel_launch(void* const* d_in, const int* in_sizes, int n_in,
                              void* d_out, int out_size)
{
    const float* x      = (const float*)d_in[0];
    const float* qkv_w  = (const float*)d_in[1];
    const float* qkv_b  = (const float*)d_in[2];
    const float* proj_w = (const float*)d_in[3];
    const float* proj_b = (const float*)d_in[4];
    const float* rpb    = (const float*)d_in[5];
    float* out = (float*)d_out;

    convert_weights<<<(12*4*12*32*4 + TPB - 1)/TPB, TPB>>>(qkv_w, proj_w);

    cudaFuncSetAttribute(swin15,
                         cudaFuncAttributeMaxDynamicSharedMemorySize, SMEM_BYTES);
    swin15<<<4096, TPB, SMEM_BYTES>>>(x, qkv_b, proj_b, rpb, out);
}

// round 16
// speedup vs baseline: 1.0734x; 1.0024x over previous
#include <cuda_runtime.h>
#include <cuda_bf16.h>

// Fused shifted-window attention (Swin), round 16.
// = round 15 EXACT (461.9us proven) with ONE change: softmax specialized for
// interior windows (96.9% of CTAs). The uniform per-CTA branch on (er|ec)
// gives the interior path a mask-free bias+exp2 chain (no ISETP, no
// predicated FADD, no region-id setup); edge windows keep the full path.

constexpr int TPB = 256;

// fragment-ordered weights: [pass(12)][ng(4)][kt(12)][lane(32)] x uint4
// pass 0..8 = qkv (9*64 out rows), pass 9..11 = proj.
__device__ uint4 g_wfrag[12 * 4 * 12 * 32];

// smem offsets (bytes)
constexpr int XBF_B = 0;       // [64][200] bf16 : gathered x, later attn-out
constexpr int QSH_B = 25600;   // [8][64][24] bf16, 48B rows
constexpr int KSH_B = 50176;   // same
constexpr int VSH_B = 74752;   // [8][24][72] bf16, 144B rows
constexpr int RPB_B = 102400;  // [8][228] f32 (pre-scaled by log2e)
constexpr int SMEM_BYTES = 109696;

__device__ __forceinline__ unsigned sptr(const void* p) {
    return (unsigned)__cvta_generic_to_shared(p);
}
__device__ __forceinline__ void ldmx4(unsigned a, unsigned* r) {
    asm volatile("ldmatrix.sync.aligned.m8n8.x4.shared.b16 {%0,%1,%2,%3}, [%4];"
        : "=r"(r[0]), "=r"(r[1]), "=r"(r[2]), "=r"(r[3]) : "r"(a));
}
__device__ __forceinline__ void ldmx2(unsigned a, unsigned* r) {
    asm volatile("ldmatrix.sync.aligned.m8n8.x2.shared.b16 {%0,%1}, [%2];"
        : "=r"(r[0]), "=r"(r[1]) : "r"(a));
}
__device__ __forceinline__ unsigned ldmx1(unsigned a) {
    unsigned r;
    asm volatile("ldmatrix.sync.aligned.m8n8.x1.shared.b16 {%0}, [%1];"
        : "=r"(r) : "r"(a));
    return r;
}
__device__ __forceinline__ void mma16(float* c, const unsigned* a, const unsigned* b) {
    asm volatile("mma.sync.aligned.m16n8k16.row.col.f32.bf16.bf16.f32 "
        "{%0,%1,%2,%3}, {%4,%5,%6,%7}, {%8,%9}, {%0,%1,%2,%3};"
        : "+f"(c[0]), "+f"(c[1]), "+f"(c[2]), "+f"(c[3])
        : "r"(a[0]), "r"(a[1]), "r"(a[2]), "r"(a[3]), "r"(b[0]), "r"(b[1]));
}
__device__ __forceinline__ void mma8(float* c, const unsigned* a, unsigned b) {
    asm volatile("mma.sync.aligned.m16n8k8.row.col.f32.bf16.bf16.f32 "
        "{%0,%1,%2,%3}, {%4,%5}, {%6}, {%0,%1,%2,%3};"
        : "+f"(c[0]), "+f"(c[1]), "+f"(c[2]), "+f"(c[3])
        : "r"(a[0]), "r"(a[1]), "r"(b));
}
__device__ __forceinline__ unsigned packbf(float a, float b) {
    __nv_bfloat162 t = __floats2bfloat162_rn(a, b);
    return *(unsigned*)&t;
}
__device__ __forceinline__ float ex2f(float x) {
    float r;
    asm("ex2.approx.f32 %0, %1;" : "=f"(r) : "f"(x));
    return r;
}

// one thread per output u32 (73728 total)
__global__ void convert_weights(const float* __restrict__ qkv_w,
                                const float* __restrict__ proj_w)
{
    int idx = blockIdx.x * TPB + threadIdx.x;
    if (idx >= 12*4*12*32*4) return;
    int q    = idx & 3;
    int tmp  = idx >> 2;          // uint4 index
    int lane = tmp & 31;
    int tmp2 = tmp >> 5;
    int kt   = tmp2 % 12;
    int tmp3 = tmp2 / 12;
    int ng   = tmp3 & 3;
    int p    = tmp3 >> 2;
    int g    = lane >> 2;
    int tig  = lane & 3;
    int j    = q >> 1;
    int half = q & 1;
    int row  = p*64 + ng*16 + j*8 + g;            // 0..767
    int col2 = kt*8 + tig + half*4;               // u32 column
    const float* src = (row < 576) ? (qkv_w + row*192)
                                   : (proj_w + (row - 576)*192);
    ((unsigned*)g_wfrag)[idx] = packbf(src[2*col2], src[2*col2 + 1]);
}

__global__ void __launch_bounds__(TPB, 2)
swin16(const float* __restrict__ x,
       const float* __restrict__ qkv_b,
       const float* __restrict__ proj_b,
       const float* __restrict__ rpb,
       float* __restrict__ out)
{
    extern __shared__ char smem[];
    __nv_bfloat16* xbf = (__nv_bfloat16*)(smem + XBF_B);
    float* rpbt = (float*)(smem + RPB_B);

    const int tid  = threadIdx.x;
    const int lane = tid & 31;
    const int wid  = tid >> 5;
    const int g    = lane >> 2;
    const int tig  = lane & 3;

    const int win = blockIdx.x;
    const int b   = win >> 10;
    const int wr  = (win >> 5) & 31;
    const int wc  = win & 31;
    const int hbase = wr*8 + 4;
    const int wbase = wc*8 + 4;
    const bool er = (wr == 31), ec = (wc == 31);
    const float LOG2E = 1.4426950408889634f;
    const float SCALE = 0.2041241452319315f * LOG2E;   // 24^-0.5 * log2(e)
    const float MASKC = 100.0f * LOG2E;

    const float* xb   = x   + ((b*192) << 16);
    float*       outb = out + ((b*192) << 16);

    // ---------------- prologue ----------------
    for (int i = tid; i < 1800; i += TPB)
        rpbt[(i & 7)*228 + (i >> 3)] = rpb[i] * LOG2E;
    for (int idx = tid; idx < 192*64; idx += TPB) {
        int c = idx >> 6, t = idx & 63;
        int hh = (hbase + (t >> 3)) & 255;
        int ww = (wbase + (t & 7)) & 255;
        xbf[t*200 + c] = __float2bfloat16(xb[(c << 16) + (hh << 8) + ww]);
    }
    __syncthreads();   // (1)

    const int mg = wid >> 2;   // 0..1 : rows mg*32
    const int ng = wid & 3;    // 0..3 : cols ng*16

    const unsigned aA0 = sptr(smem + XBF_B) + ((mg*32 + (lane & 15))*200 + (lane >> 4)*8)*2;
    const unsigned aA1 = aA0 + 16*400;

    // ===== QKV GEMM: oc unrolled (compile-time q/k/v select), pp dynamic =====
    #pragma unroll
    for (int oc = 0; oc < 3; ++oc) {
        for (int pp = 0; pp < 3; ++pp) {
            const int cbase = pp*64;
            const uint4* bp = g_wfrag + (((oc*3 + pp)*4 + ng)*12)*32 + lane;

            float acc[2][2][4];
            #pragma unroll
            for (int i = 0; i < 2; ++i)
                #pragma unroll
                for (int j = 0; j < 2; ++j)
                    acc[i][j][0]=acc[i][j][1]=acc[i][j][2]=acc[i][j][3]=0.f;

            #pragma unroll
            for (int kt = 0; kt < 12; ++kt) {
                uint4 w = bp[kt*32];
                unsigned bf0[2] = {w.x, w.y};
                unsigned bf1[2] = {w.z, w.w};
                unsigned af[2][4];
                ldmx4(aA0 + kt*32, af[0]);
                ldmx4(aA1 + kt*32, af[1]);
                mma16(acc[0][0], af[0], bf0);
                mma16(acc[0][1], af[0], bf1);
                mma16(acc[1][0], af[1], bf0);
                mma16(acc[1][1], af[1], bf1);
            }
            // epilogue -> q/k/v smem (+bias; q pre-scaled); oc compile-time
            #pragma unroll
            for (int mt = 0; mt < 2; ++mt) {
                #pragma unroll
                for (int j = 0; j < 2; ++j) {
                    int cg = cbase + ng*16 + j*8 + 2*tig;
                    int h2 = cg / 24;
                    int d  = cg - h2*24;
                    float2 bb = *(const float2*)(qkv_b + oc*192 + cg);
                    int r0 = mg*32 + mt*16 + g;
                    float c0 = acc[mt][j][0] + bb.x, c1 = acc[mt][j][1] + bb.y;
                    float c2 = acc[mt][j][2] + bb.x, c3 = acc[mt][j][3] + bb.y;
                    if (oc == 0) {
                        c0 *= SCALE; c1 *= SCALE; c2 *= SCALE; c3 *= SCALE;
                        *(__nv_bfloat162*)(smem + QSH_B + (h2*64 + r0    )*48 + d*2) = __floats2bfloat162_rn(c0, c1);
                        *(__nv_bfloat162*)(smem + QSH_B + (h2*64 + r0 + 8)*48 + d*2) = __floats2bfloat162_rn(c2, c3);
                    } else if (oc == 1) {
                        *(__nv_bfloat162*)(smem + KSH_B + (h2*64 + r0    )*48 + d*2) = __floats2bfloat162_rn(c0, c1);
                        *(__nv_bfloat162*)(smem + KSH_B + (h2*64 + r0 + 8)*48 + d*2) = __floats2bfloat162_rn(c2, c3);
                    } else {
                        __nv_bfloat16* vv = (__nv_bfloat16*)(smem + VSH_B) + (h2*24 + d)*72;
                        vv[r0]          = __float2bfloat16(c0);
                        vv[72 + r0]     = __float2bfloat16(c1);
                        vv[r0 + 8]      = __float2bfloat16(c2);
                        vv[72 + r0 + 8] = __float2bfloat16(c3);
                    }
                }
            }
        }
    }
    __syncthreads();   // (2) q/k/v visible; xbf reads done

    // ================= attention: warp h = head h, register-resident =================
    {
        const int h = wid;
        const float* rp = rpbt + h*228;
        const unsigned qb16 = sptr(smem + QSH_B) + (h*64 + (lane & 15))*48 + (lane >> 4)*16;
        const unsigned qb8  = sptr(smem + QSH_B) + (h*64 + (lane & 15))*48 + 32;
        const unsigned kb16 = sptr(smem + KSH_B) + (h*64 + (lane & 7))*48 + ((lane >> 3) & 1)*16;
        const unsigned kb8  = sptr(smem + KSH_B) + (h*64 + (lane & 7))*48 + 32;
        const unsigned vb   = sptr(smem + VSH_B) + (h*24 + (lane & 7))*144 + ((lane >> 3) & 1)*16;

        const bool edge = er | ec;
        int regjE[2];
        #pragma unroll
        for (int e = 0; e < 2; ++e)
            regjE[e] = ec ? (((2*tig + e) < 4) ? 1 : 2) : 0;
        const int regiX = ec ? ((g < 4) ? 1 : 2) : 0;

        #pragma unroll
        for (int mp = 0; mp < 2; ++mp) {
            unsigned qf[2][4], qf8v[2][2];
            #pragma unroll
            for (int mt = 0; mt < 2; ++mt) {
                ldmx4(qb16 + (mp*32 + mt*16)*48, qf[mt]);
                ldmx2(qb8  + (mp*32 + mt*16)*48, qf8v[mt]);
            }
            float s[2][8][4];
            #pragma unroll
            for (int jj = 0; jj < 8; ++jj) {
                unsigned kf[2];
                ldmx2(kb16 + jj*384, kf);
                unsigned k8 = ldmx1(kb8 + jj*384);
                #pragma unroll
                for (int mt = 0; mt < 2; ++mt) {
                    s[mt][jj][0]=s[mt][jj][1]=s[mt][jj][2]=s[mt][jj][3]=0.f;
                    mma16(s[mt][jj], qf[mt], kf);
                    mma8 (s[mt][jj], qf8v[mt], k8);
                }
            }
            // bias (+ mask only on edge windows) + exp2; normalization deferred
            float inv[2][2];
            if (!edge) {
                // interior path (96.9% of windows): no mask logic at all
                #pragma unroll
                for (int mt = 0; mt < 2; ++mt) {
                    #pragma unroll
                    for (int half = 0; half < 2; ++half) {
                        int yi = mp*4 + mt*2 + half;
                        float sum = 0.f;
                        #pragma unroll
                        for (int jj = 0; jj < 8; ++jj) {
                            #pragma unroll
                            for (int e = 0; e < 2; ++e) {
                                int idx = (yi - jj + 7)*15 + (g - (2*tig + e) + 7);
                                float ev = ex2f(s[mt][jj][half*2 + e] + rp[idx]);
                                s[mt][jj][half*2 + e] = ev;
                                sum += ev;
                            }
                        }
                        sum += __shfl_xor_sync(0xffffffffu, sum, 1);
                        sum += __shfl_xor_sync(0xffffffffu, sum, 2);
                        inv[mt][half] = 1.f / sum;
                    }
                }
            } else {
                // edge path: full region mask
                #pragma unroll
                for (int mt = 0; mt < 2; ++mt) {
                    #pragma unroll
                    for (int half = 0; half < 2; ++half) {
                        int yi = mp*4 + mt*2 + half;
                        int regi = (er ? ((yi < 4) ? 3 : 6) : 0) + regiX;
                        float sum = 0.f;
                        #pragma unroll
                        for (int jj = 0; jj < 8; ++jj) {
                            int rjY = er ? ((jj < 4) ? 3 : 6) : 0;
                            #pragma unroll
                            for (int e = 0; e < 2; ++e) {
                                float val = s[mt][jj][half*2 + e];
                                int idx = (yi - jj + 7)*15 + (g - (2*tig + e) + 7);
                                val += rp[idx];
                                if (regi != (rjY + regjE[e])) val -= MASKC;
                                float ev = ex2f(val);
                                s[mt][jj][half*2 + e] = ev;
                                sum += ev;
                            }
                        }
                        sum += __shfl_xor_sync(0xffffffffu, sum, 1);
                        sum += __shfl_xor_sync(0xffffffffu, sum, 2);
                        inv[mt][half] = 1.f / sum;
                    }
                }
            }
            // repack unnormalized P -> a-frags; O = P @ V
            unsigned pf[2][4][4];
            #pragma unroll
            for (int mt = 0; mt < 2; ++mt)
                #pragma unroll
                for (int kt = 0; kt < 4; ++kt) {
                    pf[mt][kt][0] = packbf(s[mt][2*kt][0],     s[mt][2*kt][1]);
                    pf[mt][kt][1] = packbf(s[mt][2*kt][2],     s[mt][2*kt][3]);
                    pf[mt][kt][2] = packbf(s[mt][2*kt + 1][0], s[mt][2*kt + 1][1]);
                    pf[mt][kt][3] = packbf(s[mt][2*kt + 1][2], s[mt][2*kt + 1][3]);
                }
            float o[2][3][4];
            #pragma unroll
            for (int mt = 0; mt < 2; ++mt)
                #pragma unroll
                for (int vn = 0; vn < 3; ++vn)
                    o[mt][vn][0]=o[mt][vn][1]=o[mt][vn][2]=o[mt][vn][3]=0.f;
            #pragma unroll
            for (int kt = 0; kt < 4; ++kt)
                #pragma unroll
                for (int vn = 0; vn < 3; ++vn) {
                    unsigned vf[2];
                    ldmx2(vb + vn*1152 + kt*32, vf);
                    mma16(o[0][vn], pf[0][kt], vf);
                    mma16(o[1][vn], pf[1][kt], vf);
                }
            // write O (scaled by deferred 1/sum) -> attn-out, [token][h*24+d]
            #pragma unroll
            for (int mt = 0; mt < 2; ++mt) {
                int r0 = mp*32 + mt*16 + g;
                float iv0 = inv[mt][0], iv1 = inv[mt][1];
                #pragma unroll
                for (int vn = 0; vn < 3; ++vn) {
                    int col = h*24 + vn*8 + 2*tig;
                    *(__nv_bfloat162*)(smem + XBF_B + r0*400 + col*2)
                        = __floats2bfloat162_rn(o[mt][vn][0]*iv0, o[mt][vn][1]*iv0);
                    *(__nv_bfloat162*)(smem + XBF_B + (r0 + 8)*400 + col*2)
                        = __floats2bfloat162_rn(o[mt][vn][2]*iv1, o[mt][vn][3]*iv1);
                }
            }
        }
    }
    __syncthreads();   // (3) attn-out visible

    // ================= proj GEMM + bias + residual + scatter =================
    for (int p = 0; p < 3; ++p) {
        const uint4* bp = g_wfrag + (((9 + p)*4 + ng)*12)*32 + lane;

        float acc[2][2][4];
        #pragma unroll
        for (int i = 0; i < 2; ++i)
            #pragma unroll
            for (int j = 0; j < 2; ++j)
                acc[i][j][0]=acc[i][j][1]=acc[i][j][2]=acc[i][j][3]=0.f;

        #pragma unroll
        for (int kt = 0; kt < 12; ++kt) {
            uint4 w = bp[kt*32];
            unsigned bf0[2] = {w.x, w.y};
            unsigned bf1[2] = {w.z, w.w};
            unsigned af[2][4];
            ldmx4(aA0 + kt*32, af[0]);
            ldmx4(aA1 + kt*32, af[1]);
            mma16(acc[0][0], af[0], bf0);
            mma16(acc[0][1], af[0], bf1);
            mma16(acc[1][0], af[1], bf0);
            mma16(acc[1][1], af[1], bf1);
        }
        #pragma unroll
        for (int mt = 0; mt < 2; ++mt) {
            #pragma unroll
            for (int j = 0; j < 2; ++j) {
                int ch = p*64 + ng*16 + j*8 + 2*tig;
                float2 bb = *(const float2*)(proj_b + ch);
                int r0 = mg*32 + mt*16 + g, r1 = r0 + 8;
                int a0 = (((hbase + (r0 >> 3)) & 255) << 8) | ((wbase + (r0 & 7)) & 255);
                int a1 = (((hbase + (r1 >> 3)) & 255) << 8) | ((wbase + (r1 & 7)) & 255);
                const float* xc0 = xb + (ch << 16);
                const float* xc1 = xc0 + 65536;
                float* oc0 = outb + (ch << 16);
                float* oc1 = oc0 + 65536;
                oc0[a0] = acc[mt][j][0] + bb.x + xc0[a0];
                oc1[a0] = acc[mt][j][1] + bb.y + xc1[a0];
                oc0[a1] = acc[mt][j][2] + bb.x + xc0[a1];
                oc1[a1] = acc[mt][j][3] + bb.y + xc1[a1];
            }
        }
    }
}

extern "C" void kernel_launch(void* const* d_in, const int* in_sizes, int n_in,
                              void* d_out, int out_size)
{
    const float* x      = (const float*)d_in[0];
    const float* qkv_w  = (const float*)d_in[1];
    const float* qkv_b  = (const float*)d_in[2];
    const float* proj_w = (const float*)d_in[3];
    const float* proj_b = (const float*)d_in[4];
    const float* rpb    = (const float*)d_in[5];
    float* out = (float*)d_out;

    convert_weights<<<(12*4*12*32*4 + TPB - 1)/TPB, TPB>>>(qkv_w, proj_w);

    cudaFuncSetAttribute(swin16,
                         cudaFuncAttributeMaxDynamicSharedMemorySize, SMEM_BYTES);
    swin16<<<4096, TPB, SMEM_BYTES>>>(x, qkv_b, proj_b, rpb, out);
}

// round 17
// speedup vs baseline: 1.1433x; 1.0652x over previous
#include <cuda_runtime.h>
#include <cuda_bf16.h>

// Fused shifted-window attention (Swin), round 17.
// = round 16 (460.8us proven) with A-fragment register caching: kt 0..5 A
// fragments (48 regs) loaded ONCE and reused across all 9 QKV passes (and
// reloaded once from aout for the 3 proj passes). Cuts A-ldmatrix traffic
// ~42% without moving bytes between pipes and without raising the register
// peak (attention phase still sets the 128-reg max; afc is dead by then).
// Rider: rcp.approx for the softmax 1/sum.

constexpr int TPB = 256;

// fragment-ordered weights: [pass(12)][ng(4)][kt(12)][lane(32)] x uint4
// pass 0..8 = qkv (9*64 out rows), pass 9..11 = proj.
__device__ uint4 g_wfrag[12 * 4 * 12 * 32];

// smem offsets (bytes)
constexpr int XBF_B = 0;       // [64][200] bf16 : gathered x, later attn-out
constexpr int QSH_B = 25600;   // [8][64][24] bf16, 48B rows
constexpr int KSH_B = 50176;   // same
constexpr int VSH_B = 74752;   // [8][24][72] bf16, 144B rows
constexpr int RPB_B = 102400;  // [8][228] f32 (pre-scaled by log2e)
constexpr int SMEM_BYTES = 109696;

__device__ __forceinline__ unsigned sptr(const void* p) {
    return (unsigned)__cvta_generic_to_shared(p);
}
__device__ __forceinline__ void ldmx4(unsigned a, unsigned* r) {
    asm volatile("ldmatrix.sync.aligned.m8n8.x4.shared.b16 {%0,%1,%2,%3}, [%4];"
        : "=r"(r[0]), "=r"(r[1]), "=r"(r[2]), "=r"(r[3]) : "r"(a));
}
__device__ __forceinline__ void ldmx2(unsigned a, unsigned* r) {
    asm volatile("ldmatrix.sync.aligned.m8n8.x2.shared.b16 {%0,%1}, [%2];"
        : "=r"(r[0]), "=r"(r[1]) : "r"(a));
}
__device__ __forceinline__ unsigned ldmx1(unsigned a) {
    unsigned r;
    asm volatile("ldmatrix.sync.aligned.m8n8.x1.shared.b16 {%0}, [%1];"
        : "=r"(r) : "r"(a));
    return r;
}
__device__ __forceinline__ void mma16(float* c, const unsigned* a, const unsigned* b) {
    asm volatile("mma.sync.aligned.m16n8k16.row.col.f32.bf16.bf16.f32 "
        "{%0,%1,%2,%3}, {%4,%5,%6,%7}, {%8,%9}, {%0,%1,%2,%3};"
        : "+f"(c[0]), "+f"(c[1]), "+f"(c[2]), "+f"(c[3])
        : "r"(a[0]), "r"(a[1]), "r"(a[2]), "r"(a[3]), "r"(b[0]), "r"(b[1]));
}
__device__ __forceinline__ void mma8(float* c, const unsigned* a, unsigned b) {
    asm volatile("mma.sync.aligned.m16n8k8.row.col.f32.bf16.bf16.f32 "
        "{%0,%1,%2,%3}, {%4,%5}, {%6}, {%0,%1,%2,%3};"
        : "+f"(c[0]), "+f"(c[1]), "+f"(c[2]), "+f"(c[3])
        : "r"(a[0]), "r"(a[1]), "r"(b));
}
__device__ __forceinline__ unsigned packbf(float a, float b) {
    __nv_bfloat162 t = __floats2bfloat162_rn(a, b);
    return *(unsigned*)&t;
}
__device__ __forceinline__ float ex2f(float x) {
    float r;
    asm("ex2.approx.f32 %0, %1;" : "=f"(r) : "f"(x));
    return r;
}
__device__ __forceinline__ float rcpf(float x) {
    float r;
    asm("rcp.approx.f32 %0, %1;" : "=f"(r) : "f"(x));
    return r;
}

// one thread per output u32 (73728 total)
__global__ void convert_weights(const float* __restrict__ qkv_w,
                                const float* __restrict__ proj_w)
{
    int idx = blockIdx.x * TPB + threadIdx.x;
    if (idx >= 12*4*12*32*4) return;
    int q    = idx & 3;
    int tmp  = idx >> 2;          // uint4 index
    int lane = tmp & 31;
    int tmp2 = tmp >> 5;
    int kt   = tmp2 % 12;
    int tmp3 = tmp2 / 12;
    int ng   = tmp3 & 3;
    int p    = tmp3 >> 2;
    int g    = lane >> 2;
    int tig  = lane & 3;
    int j    = q >> 1;
    int half = q & 1;
    int row  = p*64 + ng*16 + j*8 + g;            // 0..767
    int col2 = kt*8 + tig + half*4;               // u32 column
    const float* src = (row < 576) ? (qkv_w + row*192)
                                   : (proj_w + (row - 576)*192);
    ((unsigned*)g_wfrag)[idx] = packbf(src[2*col2], src[2*col2 + 1]);
}

__global__ void __launch_bounds__(TPB, 2)
swin17(const float* __restrict__ x,
       const float* __restrict__ qkv_b,
       const float* __restrict__ proj_b,
       const float* __restrict__ rpb,
       float* __restrict__ out)
{
    extern __shared__ char smem[];
    __nv_bfloat16* xbf = (__nv_bfloat16*)(smem + XBF_B);
    float* rpbt = (float*)(smem + RPB_B);

    const int tid  = threadIdx.x;
    const int lane = tid & 31;
    const int wid  = tid >> 5;
    const int g    = lane >> 2;
    const int tig  = lane & 3;

    const int win = blockIdx.x;
    const int b   = win >> 10;
    const int wr  = (win >> 5) & 31;
    const int wc  = win & 31;
    const int hbase = wr*8 + 4;
    const int wbase = wc*8 + 4;
    const bool er = (wr == 31), ec = (wc == 31);
    const float LOG2E = 1.4426950408889634f;
    const float SCALE = 0.2041241452319315f * LOG2E;   // 24^-0.5 * log2(e)
    const float MASKC = 100.0f * LOG2E;

    const float* xb   = x   + ((b*192) << 16);
    float*       outb = out + ((b*192) << 16);

    // ---------------- prologue ----------------
    for (int i = tid; i < 1800; i += TPB)
        rpbt[(i & 7)*228 + (i >> 3)] = rpb[i] * LOG2E;
    for (int idx = tid; idx < 192*64; idx += TPB) {
        int c = idx >> 6, t = idx & 63;
        int hh = (hbase + (t >> 3)) & 255;
        int ww = (wbase + (t & 7)) & 255;
        xbf[t*200 + c] = __float2bfloat16(xb[(c << 16) + (hh << 8) + ww]);
    }
    __syncthreads();   // (1)

    const int mg = wid >> 2;   // 0..1 : rows mg*32
    const int ng = wid & 3;    // 0..3 : cols ng*16

    const unsigned aA0 = sptr(smem + XBF_B) + ((mg*32 + (lane & 15))*200 + (lane >> 4)*8)*2;
    const unsigned aA1 = aA0 + 16*400;

    // cache A fragments for kt 0..5 (48 regs), reused across all 9 QKV passes
    unsigned afc[6][2][4];
    #pragma unroll
    for (int kt = 0; kt < 6; ++kt) {
        ldmx4(aA0 + kt*32, afc[kt][0]);
        ldmx4(aA1 + kt*32, afc[kt][1]);
    }

    // ===== QKV GEMM: oc unrolled (compile-time q/k/v select), pp dynamic =====
    #pragma unroll
    for (int oc = 0; oc < 3; ++oc) {
        for (int pp = 0; pp < 3; ++pp) {
            const int cbase = pp*64;
            const uint4* bp = g_wfrag + (((oc*3 + pp)*4 + ng)*12)*32 + lane;

            float acc[2][2][4];
            #pragma unroll
            for (int i = 0; i < 2; ++i)
                #pragma unroll
                for (int j = 0; j < 2; ++j)
                    acc[i][j][0]=acc[i][j][1]=acc[i][j][2]=acc[i][j][3]=0.f;

            #pragma unroll
            for (int kt = 0; kt < 6; ++kt) {
                uint4 w = bp[kt*32];
                unsigned bf0[2] = {w.x, w.y};
                unsigned bf1[2] = {w.z, w.w};
                mma16(acc[0][0], afc[kt][0], bf0);
                mma16(acc[0][1], afc[kt][0], bf1);
                mma16(acc[1][0], afc[kt][1], bf0);
                mma16(acc[1][1], afc[kt][1], bf1);
            }
            #pragma unroll
            for (int kt = 6; kt < 12; ++kt) {
                uint4 w = bp[kt*32];
                unsigned bf0[2] = {w.x, w.y};
                unsigned bf1[2] = {w.z, w.w};
                unsigned af[2][4];
                ldmx4(aA0 + kt*32, af[0]);
                ldmx4(aA1 + kt*32, af[1]);
                mma16(acc[0][0], af[0], bf0);
                mma16(acc[0][1], af[0], bf1);
                mma16(acc[1][0], af[1], bf0);
                mma16(acc[1][1], af[1], bf1);
            }
            // epilogue -> q/k/v smem (+bias; q pre-scaled); oc compile-time
            #pragma unroll
            for (int mt = 0; mt < 2; ++mt) {
                #pragma unroll
                for (int j = 0; j < 2; ++j) {
                    int cg = cbase + ng*16 + j*8 + 2*tig;
                    int h2 = cg / 24;
                    int d  = cg - h2*24;
                    float2 bb = *(const float2*)(qkv_b + oc*192 + cg);
                    int r0 = mg*32 + mt*16 + g;
                    float c0 = acc[mt][j][0] + bb.x, c1 = acc[mt][j][1] + bb.y;
                    float c2 = acc[mt][j][2] + bb.x, c3 = acc[mt][j][3] + bb.y;
                    if (oc == 0) {
                        c0 *= SCALE; c1 *= SCALE; c2 *= SCALE; c3 *= SCALE;
                        *(__nv_bfloat162*)(smem + QSH_B + (h2*64 + r0    )*48 + d*2) = __floats2bfloat162_rn(c0, c1);
                        *(__nv_bfloat162*)(smem + QSH_B + (h2*64 + r0 + 8)*48 + d*2) = __floats2bfloat162_rn(c2, c3);
                    } else if (oc == 1) {
                        *(__nv_bfloat162*)(smem + KSH_B + (h2*64 + r0    )*48 + d*2) = __floats2bfloat162_rn(c0, c1);
                        *(__nv_bfloat162*)(smem + KSH_B + (h2*64 + r0 + 8)*48 + d*2) = __floats2bfloat162_rn(c2, c3);
                    } else {
                        __nv_bfloat16* vv = (__nv_bfloat16*)(smem + VSH_B) + (h2*24 + d)*72;
                        vv[r0]          = __float2bfloat16(c0);
                        vv[72 + r0]     = __float2bfloat16(c1);
                        vv[r0 + 8]      = __float2bfloat16(c2);
                        vv[72 + r0 + 8] = __float2bfloat16(c3);
                    }
                }
            }
        }
    }
    __syncthreads();   // (2) q/k/v visible; xbf reads done

    // ================= attention: warp h = head h, register-resident =================
    {
        const int h = wid;
        const float* rp = rpbt + h*228;
        const unsigned qb16 = sptr(smem + QSH_B) + (h*64 + (lane & 15))*48 + (lane >> 4)*16;
        const unsigned qb8  = sptr(smem + QSH_B) + (h*64 + (lane & 15))*48 + 32;
        const unsigned kb16 = sptr(smem + KSH_B) + (h*64 + (lane & 7))*48 + ((lane >> 3) & 1)*16;
        const unsigned kb8  = sptr(smem + KSH_B) + (h*64 + (lane & 7))*48 + 32;
        const unsigned vb   = sptr(smem + VSH_B) + (h*24 + (lane & 7))*144 + ((lane >> 3) & 1)*16;

        const bool edge = er | ec;
        int regjE[2];
        #pragma unroll
        for (int e = 0; e < 2; ++e)
            regjE[e] = ec ? (((2*tig + e) < 4) ? 1 : 2) : 0;
        const int regiX = ec ? ((g < 4) ? 1 : 2) : 0;

        #pragma unroll
        for (int mp = 0; mp < 2; ++mp) {
            unsigned qf[2][4], qf8v[2][2];
            #pragma unroll
            for (int mt = 0; mt < 2; ++mt) {
                ldmx4(qb16 + (mp*32 + mt*16)*48, qf[mt]);
                ldmx2(qb8  + (mp*32 + mt*16)*48, qf8v[mt]);
            }
            float s[2][8][4];
            #pragma unroll
            for (int jj = 0; jj < 8; ++jj) {
                unsigned kf[2];
                ldmx2(kb16 + jj*384, kf);
                unsigned k8 = ldmx1(kb8 + jj*384);
                #pragma unroll
                for (int mt = 0; mt < 2; ++mt) {
                    s[mt][jj][0]=s[mt][jj][1]=s[mt][jj][2]=s[mt][jj][3]=0.f;
                    mma16(s[mt][jj], qf[mt], kf);
                    mma8 (s[mt][jj], qf8v[mt], k8);
                }
            }
            // bias (+ mask only on edge windows) + exp2; normalization deferred
            float inv[2][2];
            if (!edge) {
                #pragma unroll
                for (int mt = 0; mt < 2; ++mt) {
                    #pragma unroll
                    for (int half = 0; half < 2; ++half) {
                        int yi = mp*4 + mt*2 + half;
                        float sum = 0.f;
                        #pragma unroll
                        for (int jj = 0; jj < 8; ++jj) {
                            #pragma unroll
                            for (int e = 0; e < 2; ++e) {
                                int idx = (yi - jj + 7)*15 + (g - (2*tig + e) + 7);
                                float ev = ex2f(s[mt][jj][half*2 + e] + rp[idx]);
                                s[mt][jj][half*2 + e] = ev;
                                sum += ev;
                            }
                        }
                        sum += __shfl_xor_sync(0xffffffffu, sum, 1);
                        sum += __shfl_xor_sync(0xffffffffu, sum, 2);
                        inv[mt][half] = rcpf(sum);
                    }
                }
            } else {
                #pragma unroll
                for (int mt = 0; mt < 2; ++mt) {
                    #pragma unroll
                    for (int half = 0; half < 2; ++half) {
                        int yi = mp*4 + mt*2 + half;
                        int regi = (er ? ((yi < 4) ? 3 : 6) : 0) + regiX;
                        float sum = 0.f;
                        #pragma unroll
                        for (int jj = 0; jj < 8; ++jj) {
                            int rjY = er ? ((jj < 4) ? 3 : 6) : 0;
                            #pragma unroll
                            for (int e = 0; e < 2; ++e) {
                                float val = s[mt][jj][half*2 + e];
                                int idx = (yi - jj + 7)*15 + (g - (2*tig + e) + 7);
                                val += rp[idx];
                                if (regi != (rjY + regjE[e])) val -= MASKC;
                                float ev = ex2f(val);
                                s[mt][jj][half*2 + e] = ev;
                                sum += ev;
                            }
                        }
                        sum += __shfl_xor_sync(0xffffffffu, sum, 1);
                        sum += __shfl_xor_sync(0xffffffffu, sum, 2);
                        inv[mt][half] = rcpf(sum);
                    }
                }
            }
            // repack unnormalized P -> a-frags; O = P @ V
            unsigned pf[2][4][4];
            #pragma unroll
            for (int mt = 0; mt < 2; ++mt)
                #pragma unroll
                for (int kt = 0; kt < 4; ++kt) {
                    pf[mt][kt][0] = packbf(s[mt][2*kt][0],     s[mt][2*kt][1]);
                    pf[mt][kt][1] = packbf(s[mt][2*kt][2],     s[mt][2*kt][3]);
                    pf[mt][kt][2] = packbf(s[mt][2*kt + 1][0], s[mt][2*kt + 1][1]);
                    pf[mt][kt][3] = packbf(s[mt][2*kt + 1][2], s[mt][2*kt + 1][3]);
                }
            float o[2][3][4];
            #pragma unroll
            for (int mt = 0; mt < 2; ++mt)
                #pragma unroll
                for (int vn = 0; vn < 3; ++vn)
                    o[mt][vn][0]=o[mt][vn][1]=o[mt][vn][2]=o[mt][vn][3]=0.f;
            #pragma unroll
            for (int kt = 0; kt < 4; ++kt)
                #pragma unroll
                for (int vn = 0; vn < 3; ++vn) {
                    unsigned vf[2];
                    ldmx2(vb + vn*1152 + kt*32, vf);
                    mma16(o[0][vn], pf[0][kt], vf);
                    mma16(o[1][vn], pf[1][kt], vf);
                }
            // write O (scaled by deferred 1/sum) -> attn-out, [token][h*24+d]
            #pragma unroll
            for (int mt = 0; mt < 2; ++mt) {
                int r0 = mp*32 + mt*16 + g;
                float iv0 = inv[mt][0], iv1 = inv[mt][1];
                #pragma unroll
                for (int vn = 0; vn < 3; ++vn) {
                    int col = h*24 + vn*8 + 2*tig;
                    *(__nv_bfloat162*)(smem + XBF_B + r0*400 + col*2)
                        = __floats2bfloat162_rn(o[mt][vn][0]*iv0, o[mt][vn][1]*iv0);
                    *(__nv_bfloat162*)(smem + XBF_B + (r0 + 8)*400 + col*2)
                        = __floats2bfloat162_rn(o[mt][vn][2]*iv1, o[mt][vn][3]*iv1);
                }
            }
        }
    }
    __syncthreads();   // (3) attn-out visible

    // re-cache A fragments (kt 0..5) from attn-out for the proj passes
    #pragma unroll
    for (int kt = 0; kt < 6; ++kt) {
        ldmx4(aA0 + kt*32, afc[kt][0]);
        ldmx4(aA1 + kt*32, afc[kt][1]);
    }

    // ================= proj GEMM + bias + residual + scatter =================
    for (int p = 0; p < 3; ++p) {
        const uint4* bp = g_wfrag + (((9 + p)*4 + ng)*12)*32 + lane;

        float acc[2][2][4];
        #pragma unroll
        for (int i = 0; i < 2; ++i)
            #pragma unroll
            for (int j = 0; j < 2; ++j)
                acc[i][j][0]=acc[i][j][1]=acc[i][j][2]=acc[i][j][3]=0.f;

        #pragma unroll
        for (int kt = 0; kt < 6; ++kt) {
            uint4 w = bp[kt*32];
            unsigned bf0[2] = {w.x, w.y};
            unsigned bf1[2] = {w.z, w.w};
            mma16(acc[0][0], afc[kt][0], bf0);
            mma16(acc[0][1], afc[kt][0], bf1);
            mma16(acc[1][0], afc[kt][1], bf0);
            mma16(acc[1][1], afc[kt][1], bf1);
        }
        #pragma unroll
        for (int kt = 6; kt < 12; ++kt) {
            uint4 w = bp[kt*32];
            unsigned bf0[2] = {w.x, w.y};
            unsigned bf1[2] = {w.z, w.w};
            unsigned af[2][4];
            ldmx4(aA0 + kt*32, af[0]);
            ldmx4(aA1 + kt*32, af[1]);
            mma16(acc[0][0], af[0], bf0);
            mma16(acc[0][1], af[0], bf1);
            mma16(acc[1][0], af[1], bf0);
            mma16(acc[1][1], af[1], bf1);
        }
        #pragma unroll
        for (int mt = 0; mt < 2; ++mt) {
            #pragma unroll
            for (int j = 0; j < 2; ++j) {
                int ch = p*64 + ng*16 + j*8 + 2*tig;
                float2 bb = *(const float2*)(proj_b + ch);
                int r0 = mg*32 + mt*16 + g, r1 = r0 + 8;
                int a0 = (((hbase + (r0 >> 3)) & 255) << 8) | ((wbase + (r0 & 7)) & 255);
                int a1 = (((hbase + (r1 >> 3)) & 255) << 8) | ((wbase + (r1 & 7)) & 255);
                const float* xc0 = xb + (ch << 16);
                const float* xc1 = xc0 + 65536;
                float* oc0 = outb + (ch << 16);
                float* oc1 = oc0 + 65536;
                oc0[a0] = acc[mt][j][0] + bb.x + xc0[a0];
                oc1[a0] = acc[mt][j][1] + bb.y + xc1[a0];
                oc0[a1] = acc[mt][j][2] + bb.x + xc0[a1];
                oc1[a1] = acc[mt][j][3] + bb.y + xc1[a1];
            }
        }
    }
}

extern "C" void kernel_launch(void* const* d_in, const int* in_sizes, int n_in,
                              void* d_out, int out_size)
{
    const float* x      = (const float*)d_in[0];
    const float* qkv_w  = (const float*)d_in[1];
    const float* qkv_b  = (const float*)d_in[2];
    const float* proj_w = (const float*)d_in[3];
    const float* proj_b = (const float*)d_in[4];
    const float* rpb    = (const float*)d_in[5];
    float* out = (float*)d_out;

    convert_weights<<<(12*4*12*32*4 + TPB - 1)/TPB, TPB>>>(qkv_w, proj_w);

    cudaFuncSetAttribute(swin17,
                         cudaFuncAttributeMaxDynamicSharedMemorySize, SMEM_BYTES);
    swin17<<<4096, TPB, SMEM_BYTES>>>(x, qkv_b, proj_b, rpb, out);
}